// round 1
// baseline (speedup 1.0000x reference)
#include <cuda_runtime.h>
#include <cstdint>
#include <math.h>

#define B     64
#define LA    8
#define H     512
#define V     16384
#define SS    316       // PREF+PROF+STATE+CTX+REL = 10+10+10+256+30
#define CTXN  256
#define NROWS (B*LA)    // 512
#define SCALE 0.04419417382415922f   // 512^-0.5

// ---------------- device scratch (no allocations allowed) ----------------
__device__ __align__(16) float g_gen_exp[(size_t)NROWS * V];   // exp(gen logits)
__device__ float g_copy_exp[NROWS * SS];                       // exp(copy logits), 0 if masked
__device__ float g_rowsum[NROWS];                              // softmax denominators

// ---------------- K0: zero row sums -------------------------------------
__global__ void k0_zero() {
    int i = blockIdx.x * blockDim.x + threadIdx.x;
    if (i < NROWS) g_rowsum[i] = 0.f;
}

// ---------------- K1: copy logits -> exp, masked, + row sums -------------
// One block per batch b. dec_out[b] (8x512) cached in smem; each warp handles
// source positions s strided by 8.
__global__ __launch_bounds__(256) void k1_copy(const float* __restrict__ dec,
                                               const float* __restrict__ srch,
                                               const int* __restrict__ mask) {
    __shared__ float dsm[LA][H];    // 16 KB
    __shared__ float lsum[LA];
    int b = blockIdx.x;
    int tid = threadIdx.x;
    for (int i = tid; i < LA * H; i += 256) dsm[i / H][i % H] = dec[b * LA * H + i];
    if (tid < LA) lsum[tid] = 0.f;
    __syncthreads();

    int warp = tid >> 5, lane = tid & 31;
    for (int s = warp; s < SS; s += 8) {
        int m = mask[b * SS + s];
        if (m == 0) {
            if (lane < LA) g_copy_exp[(b * LA + lane) * SS + s] = 0.f;
            continue;
        }
        float acc[LA];
        #pragma unroll
        for (int l = 0; l < LA; l++) acc[l] = 0.f;
        const float* vp = srch + ((size_t)b * SS + s) * H;
        for (int h = lane; h < H; h += 32) {
            float v = vp[h];
            #pragma unroll
            for (int l = 0; l < LA; l++) acc[l] += dsm[l][h] * v;
        }
        #pragma unroll
        for (int l = 0; l < LA; l++) {
            float a = acc[l];
            #pragma unroll
            for (int off = 16; off; off >>= 1) a += __shfl_xor_sync(0xffffffffu, a, off);
            if (lane == 0) {
                float e = __expf(a * SCALE);
                g_copy_exp[(b * LA + l) * SS + s] = e;
                atomicAdd(&lsum[l], e);
            }
        }
    }
    __syncthreads();
    if (tid < LA) atomicAdd(&g_rowsum[b * LA + tid], lsum[tid]);
}

// ---------------- K2: gen GEMM + exp + row-sum epilogue ------------------
// C[512,16384] = A[512,512] x W[512,16384]; 128x128 tile, BK=16, 256 threads,
// 8x8 microtile using packed fma.rn.f32x2 (2 FLOP/inst -> full fp32 rate).
#define BK 16
__global__ __launch_bounds__(256) void k2_gemm(const float* __restrict__ A,
                                               const float* __restrict__ W,
                                               const float* __restrict__ bias) {
    __shared__ float As[BK][128];
    __shared__ float Ws[BK][128];
    __shared__ float red[16][128];

    int tid = threadIdx.x;
    int bx = blockIdx.x, by = blockIdx.y;
    int tm = tid >> 4, tn = tid & 15;   // 16x16 thread grid, 8x8 micro

    unsigned long long c2[8][4];
    #pragma unroll
    for (int i = 0; i < 8; i++)
        #pragma unroll
        for (int j = 0; j < 4; j++) c2[i][j] = 0ull;

    int arow = tid >> 2;     // 0..63
    int akq  = tid & 3;      // 0..3
    int wkr  = tid >> 5;     // 0..7
    int wnq  = tid & 31;     // 0..31
    int tq   = tn >> 2;      // swizzle phase for conflict-free LDS.64

    for (int kt = 0; kt < H; kt += BK) {
        #pragma unroll
        for (int it = 0; it < 2; it++) {
            int r = arow + it * 64;
            float4 a4 = *(const float4*)&A[(size_t)(by * 128 + r) * H + kt + akq * 4];
            As[akq * 4 + 0][r] = a4.x;
            As[akq * 4 + 1][r] = a4.y;
            As[akq * 4 + 2][r] = a4.z;
            As[akq * 4 + 3][r] = a4.w;
        }
        #pragma unroll
        for (int it = 0; it < 2; it++) {
            int kr = wkr + it * 8;
            float4 w4 = *(const float4*)&W[(size_t)(kt + kr) * V + bx * 128 + wnq * 4];
            *(float4*)&Ws[kr][wnq * 4] = w4;
        }
        __syncthreads();
        #pragma unroll
        for (int k = 0; k < BK; k++) {
            unsigned long long bvec[4];
            #pragma unroll
            for (int s = 0; s < 4; s++) {             // swizzled order: conflict-free
                int j2 = (s + tq) & 3;
                bvec[j2] = *(const unsigned long long*)&Ws[k][tn * 8 + j2 * 2];
            }
            float4 a0 = *(const float4*)&As[k][tm * 8];
            float4 a1 = *(const float4*)&As[k][tm * 8 + 4];
            float av[8] = {a0.x, a0.y, a0.z, a0.w, a1.x, a1.y, a1.z, a1.w};
            #pragma unroll
            for (int i = 0; i < 8; i++) {
                unsigned long long ad;
                asm("mov.b64 %0, {%1, %1};" : "=l"(ad) : "f"(av[i]));
                #pragma unroll
                for (int j2 = 0; j2 < 4; j2++)
                    asm("fma.rn.f32x2 %0, %1, %2, %0;"
                        : "+l"(c2[i][j2]) : "l"(ad), "l"(bvec[j2]));
            }
        }
        __syncthreads();
    }

    // epilogue: logits -> exp, store, partial row sums
    int nbase = bx * 128 + tn * 8;
    float bb[8];
    #pragma unroll
    for (int j = 0; j < 8; j++) bb[j] = bias[nbase + j];

    #pragma unroll
    for (int i = 0; i < 8; i++) {
        int r = by * 128 + tm * 8 + i;
        float e[8];
        float rs = 0.f;
        #pragma unroll
        for (int j2 = 0; j2 < 4; j2++) {
            union { unsigned long long u; float2 f; } cv;
            cv.u = c2[i][j2];
            float e0 = __expf((cv.f.x + bb[j2 * 2 + 0]) * SCALE);
            float e1 = __expf((cv.f.y + bb[j2 * 2 + 1]) * SCALE);
            e[j2 * 2 + 0] = e0;
            e[j2 * 2 + 1] = e1;
            rs += e0 + e1;
        }
        float4 s0 = make_float4(e[0], e[1], e[2], e[3]);
        float4 s1 = make_float4(e[4], e[5], e[6], e[7]);
        *(float4*)&g_gen_exp[(size_t)r * V + nbase]     = s0;
        *(float4*)&g_gen_exp[(size_t)r * V + nbase + 4] = s1;
        red[tn][tm * 8 + i] = rs;
    }
    __syncthreads();
    if (tid < 128) {
        float t = 0.f;
        #pragma unroll
        for (int j = 0; j < 16; j++) t += red[j][tid];
        atomicAdd(&g_rowsum[by * 128 + tid], t);
    }
}

// ---------------- K4: combine gen probs + dense one-hot einsums ----------
// Block = (v-chunk of 256, batch b). out = gen_exp*invZ + sum_p pc[p]*M[b,p,v]
__global__ __launch_bounds__(256) void k4_combine(const float* __restrict__ pv,
                                                  const float* __restrict__ lmat,
                                                  const float* __restrict__ tpm,
                                                  const float* __restrict__ rel,
                                                  float* __restrict__ out) {
    __shared__ float pc[60][LA];   // normalized copy probs for the 60 one-hot rows
    __shared__ float invZ[LA];
    int b = blockIdx.y;
    int tid = threadIdx.x;
    if (tid < LA) invZ[tid] = 1.f / g_rowsum[b * LA + tid];
    __syncthreads();
    if (tid < 60) {
        int src = (tid < 30) ? tid : tid + CTXN;   // skip the 256 ctx slots
        #pragma unroll
        for (int l = 0; l < LA; l++)
            pc[tid][l] = g_copy_exp[(b * LA + l) * SS + src] * invZ[l];
    }
    __syncthreads();

    int v = blockIdx.x * 256 + tid;
    float acc[LA];
    #pragma unroll
    for (int l = 0; l < LA; l++)
        acc[l] = g_gen_exp[(size_t)(b * LA + l) * V + v] * invZ[l];

    const float* pvb = pv   + (size_t)b * 10 * V + v;
    const float* lb  = lmat + (size_t)b * 10 * V + v;
    const float* tb  = tpm  + (size_t)b * 10 * V + v;
    const float* rb  = rel  + (size_t)b * 30 * V + v;
    #pragma unroll
    for (int p = 0; p < 10; p++) {
        float m0 = pvb[(size_t)p * V];
        float m1 = lb [(size_t)p * V];
        float m2 = tb [(size_t)p * V];
        #pragma unroll
        for (int l = 0; l < LA; l++)
            acc[l] += pc[p][l] * m0 + pc[10 + p][l] * m1 + pc[20 + p][l] * m2;
    }
    #pragma unroll
    for (int p = 0; p < 30; p++) {
        float m3 = rb[(size_t)p * V];
        #pragma unroll
        for (int l = 0; l < LA; l++) acc[l] += pc[30 + p][l] * m3;
    }
    #pragma unroll
    for (int l = 0; l < LA; l++)
        out[(size_t)(b * LA + l) * V + v] = acc[l];
}

// ---------------- K5: ctx scatter-add ------------------------------------
__global__ void k5_ctx(const int* __restrict__ ctx, const int* __restrict__ g2l,
                       float* __restrict__ out) {
    int b = blockIdx.x, c = threadIdx.x;   // 256 threads
    int tgt = g2l[ctx[b * CTXN + c]];
    #pragma unroll
    for (int l = 0; l < LA; l++) {
        float val = g_copy_exp[(b * LA + l) * SS + 30 + c] / g_rowsum[b * LA + l];
        atomicAdd(&out[(size_t)(b * LA + l) * V + tgt], val);
    }
}

// ---------------- launch --------------------------------------------------
extern "C" void kernel_launch(void* const* d_in, const int* in_sizes, int n_in,
                              void* d_out, int out_size) {
    const float* dec  = (const float*)d_in[0];   // [64,8,512]
    const float* srch = (const float*)d_in[1];   // [64,316,512]
    const int*   mask = (const int*)  d_in[2];   // [64,1,316]
    const float* pv   = (const float*)d_in[3];   // [64,10,16384]
    const float* lmat = (const float*)d_in[4];   // [64,10,16384]
    const float* tpm  = (const float*)d_in[5];   // [64,10,16384]
    const float* rel  = (const float*)d_in[6];   // [64,30,16384]
    const float* W    = (const float*)d_in[7];   // [512,16384]
    const float* bias = (const float*)d_in[8];   // [16384]
    const int*   ctx  = (const int*)  d_in[9];   // [64,256]
    const int*   g2l  = (const int*)  d_in[10];  // [50000]
    float* out = (float*)d_out;                  // [64,8,16384]

    k0_zero<<<2, 256>>>();
    k1_copy<<<B, 256>>>(dec, srch, mask);
    k2_gemm<<<dim3(V / 128, NROWS / 128), 256>>>(dec, W, bias);
    k4_combine<<<dim3(V / 256, B), 256>>>(pv, lmat, tpm, rel, out);
    k5_ctx<<<B, CTXN>>>(ctx, g2l, out);
}